// round 8
// baseline (speedup 1.0000x reference)
#include <cuda_runtime.h>
#include <cuda_bf16.h>
#include <cstdint>

// Problem constants (fixed shapes)
#define B_  2
#define C_  32
#define T_  8
#define H_  32
#define W_  32
#define V_  8192
#define N_  16384          // B*T*H*W query rows
#define NELEM_ 524288      // B*C*T*H*W
#define THW_ 8192          // T*H*W

#define KU_ 96             // unique K slots: [v1(32) | v2(32) | v3(32)]
#define KSU_ 12            // unique k-steps of 8
#define TILEB_ 768         // floats per 8-code fragment-interleaved B tile
#define CHCODES_ 16
#define CHFLOATS_ (2 * TILEB_)         // 1536 floats per chunk (2 tiles)
#define NCHUNKS_ (V_ / CHCODES_)       // 512

typedef unsigned long long u64;
typedef unsigned int u32;

// ---------------- device scratch ----------------
__device__ float g_A2[N_ * KU_];       // 6.3 MB: [row][96] = q1|q2|q3
__device__ float g_B2[V_ * KU_];       // 3.1 MB: fragment-interleaved 8-code tiles
__device__ float g_hee[V_];            // 0.5*||e||^2 (exact fp32)
__device__ int   g_idx[N_];
__device__ int   g_counts[V_];
__device__ float g_g[NELEM_];
__device__ float g_loss;
__device__ int   g_used;

// ---------------- helpers ----------------
__device__ __forceinline__ float tf32r(float v) {
    u32 b;
    asm("cvt.rn.tf32.f32 %0, %1;" : "=r"(b) : "f"(v));
    return __uint_as_float(b);
}
__device__ __forceinline__ u32 smem_u32(const void* p) {
    u32 a;
    asm("{ .reg .u64 t; cvta.to.shared.u64 t, %1; cvt.u32.u64 %0, t; }"
        : "=r"(a) : "l"(p));
    return a;
}
__device__ __forceinline__ void cpasync16(u32 smem, const void* gmem) {
    asm volatile("cp.async.cg.shared.global [%0], [%1], 16;" :: "r"(smem), "l"(gmem));
}
__device__ __forceinline__ void cpcommit() {
    asm volatile("cp.async.commit_group;");
}
__device__ __forceinline__ void cpwait0() {
    asm volatile("cp.async.wait_group 0;");
}
__device__ __forceinline__ void mma_tf32(
    float& d0, float& d1, float& d2, float& d3,
    u32 a0, u32 a1, u32 a2, u32 a3, u32 b0, u32 b1)
{
    asm volatile(
        "mma.sync.aligned.m16n8k8.row.col.f32.tf32.tf32.f32 "
        "{%0,%1,%2,%3}, {%4,%5,%6,%7}, {%8,%9}, {%0,%1,%2,%3};"
        : "+f"(d0), "+f"(d1), "+f"(d2), "+f"(d3)
        : "r"(a0), "r"(a1), "r"(a2), "r"(a3), "r"(b0), "r"(b1));
}

// ---------------- prep: A rows = [q1 | q2 | q3] (all tf32-truncation-safe) ----
__global__ void prep_q_kernel(const float* __restrict__ f) {
    int row = blockIdx.x * blockDim.x + threadIdx.x;
    if (row >= N_) return;
    int b = row >> 13;
    int thw = row & 8191;
    const float* fq = f + b * (C_ * THW_) + thw;
    float* dst = g_A2 + row * KU_;
#pragma unroll
    for (int ch = 0; ch < 32; ch++) {
        float v = fq[ch * THW_];
        float v1 = tf32r(v);
        float r  = v - v1;          // exact
        float v2 = tf32r(r);
        float v3 = r - v2;          // exact, <=3 significand bits
        dst[ch]      = v1;
        dst[32 + ch] = v2;
        dst[64 + ch] = v3;
    }
}

// ---------------- prep: B tiles (fragment-interleaved) + hee + zero counters --
__global__ void prep_codes_kernel(const float* __restrict__ emb) {
    int code = blockIdx.x * blockDim.x + threadIdx.x;
    if (code >= V_) return;
    g_counts[code] = 0;
    if (code == 0) { g_loss = 0.f; g_used = 0; }
    const float* e = emb + code * C_;
    float* base = g_B2 + (code >> 3) * TILEB_;
    const int g = code & 7;
    float ee = 0.f;
#pragma unroll
    for (int ch = 0; ch < 32; ch++) {
        float v = e[ch];
        ee = fmaf(v, v, ee);
        float v1 = tf32r(v);
        float r  = v - v1;
        float v2 = tf32r(r);
        float v3 = r - v2;
        // write UK = ch (e1), 32+ch (e2), 64+ch (e3) in fragment layout:
        // off = ((ks*8 + g)*4 + tg)*2 + half; ks=UK>>3, tg=UK&3, half=(UK>>2)&1
#pragma unroll
        for (int t = 0; t < 3; t++) {
            int UK = t * 32 + ch;
            float val = (t == 0) ? v1 : ((t == 1) ? v2 : v3);
            int ks = UK >> 3, tg = UK & 3, half = (UK >> 2) & 1;
            base[((ks * 8 + g) * 4 + tg) * 2 + half] = val;
        }
    }
    g_hee[code] = 0.5f * ee;
}

// ---------------- tensor-core argmin (argmax of q.e - hee) ----------------
// 128 threads = 4 warps; warp w owns rows [blk*128 + w*32, +32) as 2 m16 tiles.
// Sweeps V codes in 16-code chunks (2 n8 tiles), double-buffered cp.async.
__global__ __launch_bounds__(128) void tc_argmin_kernel() {
    __shared__ __align__(16) float bsm[2][CHFLOATS_];
    __shared__ __align__(16) float hee_s[V_];

    const int tid = threadIdx.x;
    const int lane = tid & 31;
    const int w = tid >> 5;
    const int g = lane >> 2;
    const int tg = lane & 3;
    const int rowbase = blockIdx.x * 128 + w * 32;

    // resident A fragments: af[ks][mt][r]
    u32 af[KSU_][2][4];
#pragma unroll
    for (int mt = 0; mt < 2; mt++) {
        const float* a0 = g_A2 + (rowbase + mt * 16 + g) * KU_;
        const float* a1 = g_A2 + (rowbase + mt * 16 + 8 + g) * KU_;
#pragma unroll
        for (int ks = 0; ks < KSU_; ks++) {
            af[ks][mt][0] = __float_as_uint(a0[ks * 8 + tg]);
            af[ks][mt][1] = __float_as_uint(a1[ks * 8 + tg]);
            af[ks][mt][2] = __float_as_uint(a0[ks * 8 + tg + 4]);
            af[ks][mt][3] = __float_as_uint(a1[ks * 8 + tg + 4]);
        }
    }

    const u32 sb = smem_u32(&bsm[0][0]);
    const u32 sh = smem_u32(&hee_s[0]);

    // prefetch hee table + chunk 0
    {
        const float4* hsrc = reinterpret_cast<const float4*>(g_hee);
        for (int k = tid; k < V_ / 4; k += 128)
            cpasync16(sh + k * 16, hsrc + k);
        const float4* bsrc = reinterpret_cast<const float4*>(g_B2);
        for (int k = tid; k < CHFLOATS_ / 4; k += 128)
            cpasync16(sb + k * 16, bsrc + k);
        cpcommit();
    }

    float bv[4];
    int   bi[4];
#pragma unroll
    for (int r = 0; r < 4; r++) { bv[r] = -3.402823466e+38f; bi[r] = 0; }

#pragma unroll 1
    for (int c = 0; c < NCHUNKS_; c++) {
        cpwait0();
        __syncthreads();

        if (c + 1 < NCHUNKS_) {
            const float4* src = reinterpret_cast<const float4*>(
                g_B2 + (c + 1) * CHFLOATS_);
            u32 dst = sb + ((c + 1) & 1) * (CHFLOATS_ * 4);
            for (int k = tid; k < CHFLOATS_ / 4; k += 128)
                cpasync16(dst + k * 16, src + k);
            cpcommit();
        }

        const float* bb = &bsm[c & 1][0];
        float2 bf[2][KSU_];
#pragma unroll
        for (int nt = 0; nt < 2; nt++)
#pragma unroll
            for (int ks = 0; ks < KSU_; ks++)
                bf[nt][ks] = *reinterpret_cast<const float2*>(
                    bb + nt * TILEB_ + ((ks * 8 + g) * 4 + tg) * 2);

        float acc[2][2][4];
#pragma unroll
        for (int mt = 0; mt < 2; mt++)
#pragma unroll
            for (int nt = 0; nt < 2; nt++)
#pragma unroll
                for (int r = 0; r < 4; r++) acc[mt][nt][r] = 0.f;

#pragma unroll
        for (int j = 0; j < 4; j++) {
            const int pa[6] = { j, 4 + j, 8 + j, j, 4 + j, j };
            const int pb[6] = { j, j, j, 4 + j, 4 + j, 8 + j };
#pragma unroll
            for (int t = 0; t < 6; t++)
#pragma unroll
                for (int mt = 0; mt < 2; mt++)
#pragma unroll
                    for (int nt = 0; nt < 2; nt++)
                        mma_tf32(acc[mt][nt][0], acc[mt][nt][1],
                                 acc[mt][nt][2], acc[mt][nt][3],
                                 af[pa[t]][mt][0], af[pa[t]][mt][1],
                                 af[pa[t]][mt][2], af[pa[t]][mt][3],
                                 __float_as_uint(bf[nt][pb[t]].x),
                                 __float_as_uint(bf[nt][pb[t]].y));
        }

        // epilogue: exact fp32 bias subtract + running argmax
        const int cbase = c * CHCODES_;
#pragma unroll
        for (int mt = 0; mt < 2; mt++) {
#pragma unroll
            for (int nt = 0; nt < 2; nt++) {
                const int c0 = cbase + nt * 8 + 2 * tg;
                float h0 = hee_s[c0], h1 = hee_s[c0 + 1];
                float s0 = acc[mt][nt][0] - h0;
                float s1 = acc[mt][nt][1] - h1;
                float s2 = acc[mt][nt][2] - h0;
                float s3 = acc[mt][nt][3] - h1;
                if (s0 > bv[mt * 2])     { bv[mt * 2] = s0;     bi[mt * 2] = c0; }
                if (s1 > bv[mt * 2])     { bv[mt * 2] = s1;     bi[mt * 2] = c0 + 1; }
                if (s2 > bv[mt * 2 + 1]) { bv[mt * 2 + 1] = s2; bi[mt * 2 + 1] = c0; }
                if (s3 > bv[mt * 2 + 1]) { bv[mt * 2 + 1] = s3; bi[mt * 2 + 1] = c0 + 1; }
            }
        }
    }

    // reduce across the 4 tg threads (disjoint code subsets, same rows)
#pragma unroll
    for (int off = 1; off < 4; off <<= 1) {
#pragma unroll
        for (int r = 0; r < 4; r++) {
            float v2 = __shfl_xor_sync(0xffffffffu, bv[r], off);
            int   i2 = __shfl_xor_sync(0xffffffffu, bi[r], off);
            if (v2 > bv[r] || (v2 == bv[r] && i2 < bi[r])) { bv[r] = v2; bi[r] = i2; }
        }
    }
    if (tg == 0) {
#pragma unroll
        for (int r = 0; r < 4; r++) {
            int row = rowbase + (r >> 1) * 16 + (r & 1) * 8 + g;
            g_idx[row] = bi[r];
            atomicAdd(&g_counts[bi[r]], 1);
        }
    }
}

// ---------------- gather emb rows into NCDHW field ----------------
__global__ void gather_kernel(const float* __restrict__ emb) {
    int i = blockIdx.x * blockDim.x + threadIdx.x;
    if (i >= NELEM_) return;
    int b = i / (C_ * THW_);
    int c = (i / THW_) & (C_ - 1);
    int thw = i & (THW_ - 1);
    int rowq = b * THW_ + thw;
    g_g[i] = emb[g_idx[rowq] * C_ + c];
}

// ---------------- conv3d 3x3x3 SAME + blend + mse partial ----------------
__global__ __launch_bounds__(512) void conv_kernel(
    const float* __restrict__ f, const float* __restrict__ cw,
    const float* __restrict__ cbias, float* __restrict__ out)
{
    __shared__ float ps[8 * 3 * 6 * 34];
    __shared__ float ws[8 * 27 * 32];
    __shared__ float bias_s[32];
    __shared__ float red[16];

    const int tid = threadIdx.x;
    const int bi = blockIdx.x;
    const int ht = bi & 7;
    const int t  = (bi >> 3) & 7;
    const int b  = bi >> 6;
    const int h0 = ht * 4;
    const int w   = tid & 31;
    const int hl  = (tid >> 5) & 3;
    const int cog = tid >> 7;

    if (tid < 32) bias_s[tid] = cbias[tid];

    float acc[8];
#pragma unroll
    for (int i = 0; i < 8; i++) acc[i] = 0.f;

#pragma unroll 1
    for (int ci0 = 0; ci0 < 32; ci0 += 8) {
        __syncthreads();
        for (int i = tid; i < 8 * 3 * 6 * 34; i += 512) {
            int ww = i % 34;
            int r2 = i / 34;
            int hh = r2 % 6; r2 /= 6;
            int tt = r2 % 3;
            int cil = r2 / 3;
            int gt = t + tt - 1, gh = h0 + hh - 1, gw = ww - 1;
            float v = 0.f;
            if (gt >= 0 && gt < T_ && gh >= 0 && gh < H_ && gw >= 0 && gw < W_)
                v = g_g[b * (C_ * THW_) + (ci0 + cil) * THW_ + gt * 1024 + gh * 32 + gw];
            ps[i] = v;
        }
        for (int i = tid; i < 8 * 27 * 32; i += 512) {
            int co = i & 31;
            int r2 = i >> 5;
            int kk = r2 % 27;
            int cil = r2 / 27;
            ws[i] = cw[(co * 32 + ci0 + cil) * 27 + kk];
        }
        __syncthreads();

#pragma unroll 1
        for (int cil = 0; cil < 8; cil++) {
#pragma unroll 1
            for (int kt = 0; kt < 3; kt++) {
#pragma unroll
                for (int kh = 0; kh < 3; kh++) {
#pragma unroll
                    for (int kw = 0; kw < 3; kw++) {
                        float pv = ps[((cil * 3 + kt) * 6 + hl + kh) * 34 + w + kw];
                        const float4* wv = reinterpret_cast<const float4*>(
                            &ws[(cil * 27 + (kt * 9 + kh * 3 + kw)) * 32 + cog * 8]);
                        float4 w0 = wv[0];
                        float4 w1 = wv[1];
                        acc[0] = fmaf(pv, w0.x, acc[0]);
                        acc[1] = fmaf(pv, w0.y, acc[1]);
                        acc[2] = fmaf(pv, w0.z, acc[2]);
                        acc[3] = fmaf(pv, w0.w, acc[3]);
                        acc[4] = fmaf(pv, w1.x, acc[4]);
                        acc[5] = fmaf(pv, w1.y, acc[5]);
                        acc[6] = fmaf(pv, w1.z, acc[6]);
                        acc[7] = fmaf(pv, w1.w, acc[7]);
                    }
                }
            }
        }
    }

    const int h = h0 + hl;
    float sq = 0.f;
    const int base = b * (C_ * THW_) + t * 1024 + h * 32 + w;
#pragma unroll
    for (int i = 0; i < 8; i++) {
        int co = cog * 8 + i;
        int o = base + co * THW_;
        float gv = g_g[o];
        float val = 0.5f * gv + 0.5f * (acc[i] + bias_s[co]);
        out[o] = val;
        float d = val - f[o];
        sq = fmaf(d, d, sq);
    }
#pragma unroll
    for (int off = 16; off > 0; off >>= 1)
        sq += __shfl_down_sync(0xffffffffu, sq, off);
    if ((tid & 31) == 0) red[tid >> 5] = sq;
    __syncthreads();
    if (tid == 0) {
        float s = 0.f;
#pragma unroll
        for (int i = 0; i < 16; i++) s += red[i];
        atomicAdd(&g_loss, s);
    }
}

// ---------------- usage count ----------------
__global__ void usage_kernel() {
    int v = blockIdx.x * blockDim.x + threadIdx.x;
    bool u = (v < V_) && (g_counts[v] > 0);
    unsigned m = __ballot_sync(0xffffffffu, u);
    if ((threadIdx.x & 31) == 0) atomicAdd(&g_used, __popc(m));
}

// ---------------- finalize scalars ----------------
__global__ void finalize_kernel(float* __restrict__ out, int write_scalars) {
    if (!write_scalars) return;
    out[NELEM_]     = 1.25f * g_loss * (1.0f / (float)NELEM_);
    out[NELEM_ + 1] = 100.0f * (float)g_used / (float)V_;
}

extern "C" void kernel_launch(void* const* d_in, const int* in_sizes, int n_in,
                              void* d_out, int out_size) {
    const float* f    = (const float*)d_in[0];
    const float* emb  = (const float*)d_in[1];
    const float* cw   = (const float*)d_in[2];
    const float* cb   = (const float*)d_in[3];
    float* out = (float*)d_out;
    int write_scalars = (out_size >= NELEM_ + 2) ? 1 : 0;

    prep_q_kernel<<<N_ / 256, 256>>>(f);
    prep_codes_kernel<<<V_ / 256, 256>>>(emb);
    tc_argmin_kernel<<<N_ / 128, 128>>>();
    gather_kernel<<<NELEM_ / 256, 256>>>(emb);
    conv_kernel<<<B_ * T_ * (H_ / 4), 512>>>(f, cw, cb, out);
    usage_kernel<<<V_ / 256, 256>>>();
    finalize_kernel<<<1, 1>>>(out, write_scalars);
}